// round 4
// baseline (speedup 1.0000x reference)
#include <cuda_runtime.h>
#include <cstdint>

#define XN 32
#define CIN 256
#define HIN 56
#define WIN 56
#define S_IN (HIN * WIN)      // 3136
#define COUT 256
#define HOUT 28
#define WOUT 28
#define S_OUT (HOUT * WOUT)   // 784
#define M_TOTAL (XN * S_OUT)  // 25088
#define X_ELEMS (XN * CIN * S_IN)  // 25690112

// Device scratch (no cudaMalloc allowed)
__device__ __align__(16) signed char g_xq[(size_t)XN * S_IN * CIN];   // ~25.7 MB, NHWC int8
__device__ __align__(16) signed char g_wq[(size_t)COUT * 9 * CIN];    // [co][tap][ci] int8

// ---------------------------------------------------------------------------
// Kernel 1: quantize x (round-half-even, clamp [-128,127]) + NCHW -> N(S)C
// transpose via smem tile. Tile: 128 channels x 32 spatial.
// ---------------------------------------------------------------------------
__global__ void quant_x_kernel(const float* __restrict__ x) {
    __shared__ signed char tile[32 * 132];  // [s][c], pitch 132 -> conflict-free
    const int n  = blockIdx.z;
    const int c0 = blockIdx.y * 128;
    const int s0 = blockIdx.x * 32;
    const int t  = threadIdx.x;

    const float* xb = x + (size_t)n * CIN * S_IN;
#pragma unroll
    for (int it = 0; it < 16; ++it) {
        int i  = it * 256 + t;
        int cl = i >> 5;   // 0..127
        int sl = i & 31;   // 0..31
        float v = xb[(size_t)(c0 + cl) * S_IN + (s0 + sl)];
        float q = rintf(__fdiv_rn(v, 0.05f));        // matches jnp.round(x/0.05)
        q = fminf(fmaxf(q, -128.0f), 127.0f);
        tile[sl * 132 + cl] = (signed char)(int)q;
    }
    __syncthreads();

    signed char* ob = g_xq + ((size_t)n * S_IN + s0) * CIN + c0;
#pragma unroll
    for (int it = 0; it < 4; ++it) {
        int j  = it * 256 + t;
        int sl = j >> 5;
        int c4 = j & 31;
        uint32_t val = *(const uint32_t*)&tile[sl * 132 + c4 * 4];
        *(uint32_t*)&ob[(size_t)sl * CIN + c4 * 4] = val;
    }
}

// ---------------------------------------------------------------------------
// Kernel 2: weights OIHW fp32 (int-valued) -> [co][tap][ci] int8
// ---------------------------------------------------------------------------
__global__ void quant_w_kernel(const float* __restrict__ w) {
    int idx = blockIdx.x * blockDim.x + threadIdx.x;
    if (idx >= COUT * 9 * CIN) return;
    int co  = idx / (9 * CIN);
    int r   = idx - co * 9 * CIN;
    int tap = r >> 8;    // /256
    int ci  = r & 255;
    float v = w[(size_t)co * CIN * 9 + (size_t)ci * 9 + tap];
    g_wq[idx] = (signed char)(int)rintf(v);
}

// ---------------------------------------------------------------------------
// Kernel 3: implicit GEMM conv, int8 mma.sync m16n8k32.
// CTA tile 128(M) x 128(N). 8 warps: 4 (M) x 2 (N), warp tile 32x64.
// K loop: 9 taps x 4 chunks of 64 channels (2 x k32 per chunk).
// Smem pitch 80B => all fragment LDS conflict-free.
// A-fragment register order (PTX m16n8k32.s8):
//   a0: (row g,   k-lo)   a1: (row g+8, k-lo)
//   a2: (row g,   k-hi)   a3: (row g+8, k-hi)
// ---------------------------------------------------------------------------
__global__ void __launch_bounds__(256, 2) conv_mma_kernel(float* __restrict__ out) {
    __shared__ signed char As[128 * 80];
    __shared__ signed char Bs[128 * 80];

    const int t      = threadIdx.x;
    const int lane   = t & 31;
    const int wid    = t >> 5;
    const int warp_m = wid & 3;   // 0..3
    const int warp_n = wid >> 2;  // 0..1
    const int m0     = blockIdx.x * 128;
    const int co0    = blockIdx.y * 128;

    // Loader mapping: thread t services rows (t/4) and (t/4 + 64), segment t%4 (16B each)
    const int lrow = t >> 2;
    const int lseg = t & 3;

    int ln[2], lho[2], lwo[2];
#pragma unroll
    for (int i = 0; i < 2; ++i) {
        int m   = m0 + lrow + i * 64;
        int n   = m / S_OUT;
        int rem = m - n * S_OUT;
        int ho  = rem / WOUT;
        ln[i]  = n;
        lho[i] = ho;
        lwo[i] = rem - ho * WOUT;
    }

    int acc[2][8][4];
#pragma unroll
    for (int mi = 0; mi < 2; ++mi)
#pragma unroll
        for (int ni = 0; ni < 8; ++ni)
#pragma unroll
            for (int k = 0; k < 4; ++k) acc[mi][ni][k] = 0;

    for (int kh = 0; kh < 3; ++kh) {
        for (int kw = 0; kw < 3; ++kw) {
            const int tap = kh * 3 + kw;

            const signed char* aptr[2];
            const signed char* bptr[2];
            bool avalid[2];
#pragma unroll
            for (int i = 0; i < 2; ++i) {
                int hi = 2 * lho[i] + kh - 1;
                int wi = 2 * lwo[i] + kw - 1;
                avalid[i] = ((unsigned)hi < (unsigned)HIN) && ((unsigned)wi < (unsigned)WIN);
                aptr[i] = g_xq + ((size_t)ln[i] * S_IN + (size_t)hi * WIN + wi) * CIN;
                bptr[i] = g_wq + ((size_t)(co0 + lrow + i * 64) * 9 + tap) * CIN;
            }

#pragma unroll 1
            for (int kc = 0; kc < 4; ++kc) {
                __syncthreads();
                const int koff = kc * 64 + lseg * 16;
#pragma unroll
                for (int i = 0; i < 2; ++i) {
                    int4 av = avalid[i] ? *(const int4*)(aptr[i] + koff)
                                        : make_int4(0, 0, 0, 0);
                    *(int4*)&As[(lrow + i * 64) * 80 + lseg * 16] = av;
                    int4 bv = *(const int4*)(bptr[i] + koff);
                    *(int4*)&Bs[(lrow + i * 64) * 80 + lseg * 16] = bv;
                }
                __syncthreads();

#pragma unroll
                for (int k2 = 0; k2 < 2; ++k2) {
                    const int kb = k2 * 32;
                    uint32_t a[2][4];
#pragma unroll
                    for (int mi = 0; mi < 2; ++mi) {
                        int r = warp_m * 32 + mi * 16 + (lane >> 2);
                        const signed char* p = &As[r * 80 + kb + (lane & 3) * 4];
                        a[mi][0] = *(const uint32_t*)p;                  // row r,   k-lo
                        a[mi][1] = *(const uint32_t*)(p + 8 * 80);       // row r+8, k-lo
                        a[mi][2] = *(const uint32_t*)(p + 16);           // row r,   k-hi
                        a[mi][3] = *(const uint32_t*)(p + 8 * 80 + 16);  // row r+8, k-hi
                    }
#pragma unroll
                    for (int ni = 0; ni < 8; ++ni) {
                        int rn = warp_n * 64 + ni * 8 + (lane >> 2);
                        const signed char* p = &Bs[rn * 80 + kb + (lane & 3) * 4];
                        uint32_t b0 = *(const uint32_t*)p;
                        uint32_t b1 = *(const uint32_t*)(p + 16);
#pragma unroll
                        for (int mi = 0; mi < 2; ++mi) {
                            asm volatile(
                                "mma.sync.aligned.m16n8k32.row.col.s32.s8.s8.s32 "
                                "{%0,%1,%2,%3}, {%4,%5,%6,%7}, {%8,%9}, {%0,%1,%2,%3};\n"
                                : "+r"(acc[mi][ni][0]), "+r"(acc[mi][ni][1]),
                                  "+r"(acc[mi][ni][2]), "+r"(acc[mi][ni][3])
                                : "r"(a[mi][0]), "r"(a[mi][1]), "r"(a[mi][2]), "r"(a[mi][3]),
                                  "r"(b0), "r"(b1));
                        }
                    }
                }
            }
        }
    }

    // Epilogue: dequantize and store NCHW fp32.
    const float sc = (float)(0.05 * 0.01);
#pragma unroll
    for (int mi = 0; mi < 2; ++mi) {
#pragma unroll
        for (int rr = 0; rr < 2; ++rr) {
            int m = m0 + warp_m * 32 + mi * 16 + (lane >> 2) + rr * 8;
            int n = m / S_OUT;
            int s = m - n * S_OUT;
            float* op = out + (size_t)n * COUT * S_OUT + s;
#pragma unroll
            for (int ni = 0; ni < 8; ++ni) {
                int co = co0 + warp_n * 64 + ni * 8 + (lane & 3) * 2;
                op[(size_t)co * S_OUT]       = (float)acc[mi][ni][rr * 2 + 0] * sc;
                op[(size_t)(co + 1) * S_OUT] = (float)acc[mi][ni][rr * 2 + 1] * sc;
            }
        }
    }
}

// ---------------------------------------------------------------------------
extern "C" void kernel_launch(void* const* d_in, const int* in_sizes, int n_in,
                              void* d_out, int out_size) {
    const float* x = (const float*)d_in[0];
    const float* w = (const float*)d_in[1];
    // Robustness: identify x by element count (x has 25,690,112 elems; w 589,824)
    if (n_in >= 2 && in_sizes[0] != X_ELEMS) {
        const float* tmp = x; x = w; w = tmp;
    }
    float* out = (float*)d_out;

    dim3 g1(S_IN / 32, CIN / 128, XN);  // (98, 2, 32)
    quant_x_kernel<<<g1, 256>>>(x);

    quant_w_kernel<<<(COUT * 9 * CIN + 255) / 256, 256>>>(w);

    dim3 g3(M_TOTAL / 128, COUT / 128);  // (196, 2)
    conv_mma_kernel<<<g3, 256>>>(out);
}

// round 5
// speedup vs baseline: 1.1674x; 1.1674x over previous
#include <cuda_runtime.h>
#include <cstdint>

#define XN 32
#define CIN 256
#define HIN 56
#define WIN 56
#define S_IN (HIN * WIN)      // 3136
#define COUT 256
#define HOUT 28
#define WOUT 28
#define S_OUT (HOUT * WOUT)   // 784
#define M_TOTAL (XN * S_OUT)  // 25088
#define X_ELEMS (XN * CIN * S_IN)  // 25690112

// Device scratch (no cudaMalloc allowed)
__device__ __align__(16) signed char g_xq[(size_t)XN * S_IN * CIN];   // ~25.7 MB, NHWC int8
__device__ __align__(16) signed char g_wq[(size_t)COUT * 9 * CIN];    // [co][tap][ci] int8

// ---------------------------------------------------------------------------
// Kernel 1: quantize x (round-half-even via F2I.RN, clamp [-128,127]) +
// NCHW -> N(S)C transpose via smem tile. Tile: 128 channels x 32 spatial.
// x/0.05f replaced by x*20.0f (1/0.05f rounds exactly to 20.0f; <=1ulp diff).
// ---------------------------------------------------------------------------
__global__ void quant_x_kernel(const float* __restrict__ x) {
    __shared__ signed char tile[32 * 132];  // [s][c], pitch 132 -> conflict-free
    const int n  = blockIdx.z;
    const int c0 = blockIdx.y * 128;
    const int s0 = blockIdx.x * 32;
    const int t  = threadIdx.x;

    const float* xb = x + (size_t)n * CIN * S_IN;
#pragma unroll
    for (int it = 0; it < 16; ++it) {
        int i  = it * 256 + t;
        int cl = i >> 5;   // 0..127
        int sl = i & 31;   // 0..31
        float v = xb[(size_t)(c0 + cl) * S_IN + (s0 + sl)];
        int q = __float2int_rn(v * 20.0f);   // round-half-even, matches jnp.round
        q = max(-128, min(127, q));
        tile[sl * 132 + cl] = (signed char)q;
    }
    __syncthreads();

    signed char* ob = g_xq + ((size_t)n * S_IN + s0) * CIN + c0;
#pragma unroll
    for (int it = 0; it < 4; ++it) {
        int j  = it * 256 + t;
        int sl = j >> 5;
        int c4 = j & 31;
        uint32_t val = *(const uint32_t*)&tile[sl * 132 + c4 * 4];
        *(uint32_t*)&ob[(size_t)sl * CIN + c4 * 4] = val;
    }
}

// ---------------------------------------------------------------------------
// Kernel 2: weights OIHW fp32 (int-valued) -> [co][tap][ci] int8
// ---------------------------------------------------------------------------
__global__ void quant_w_kernel(const float* __restrict__ w) {
    int idx = blockIdx.x * blockDim.x + threadIdx.x;
    if (idx >= COUT * 9 * CIN) return;
    int co  = idx / (9 * CIN);
    int r   = idx - co * 9 * CIN;
    int tap = r >> 8;    // /256
    int ci  = r & 255;
    float v = w[(size_t)co * CIN * 9 + (size_t)ci * 9 + tap];
    g_wq[idx] = (signed char)__float2int_rn(v);
}

// ---------------------------------------------------------------------------
// Kernel 3: implicit GEMM conv, int8 mma.sync m16n8k32, cp.async double-buffer
// pipeline + ldmatrix fragment loads.
// CTA tile 128(M) x 128(N). 8 warps: 4(M) x 2(N), warp tile 32x64.
// K: 36 chunks = 9 taps x 4 sub-chunks of 64 channels (2 x k32 per chunk).
// Smem pitch 80B: conflict-free for ldmatrix (8 rows x 20 words cover 32 banks)
// ---------------------------------------------------------------------------
#define PITCH 80
#define STG_BYTES (128 * PITCH)   // 10240 per stage

__device__ __forceinline__ void cp16(uint32_t dst, const void* src, int sz) {
    asm volatile("cp.async.ca.shared.global [%0], [%1], 16, %2;\n"
                 :: "r"(dst), "l"(src), "r"(sz));
}

#define LDSM4(r0, r1, r2, r3, addr)                                          \
    asm volatile("ldmatrix.sync.aligned.m8n8.x4.shared.b16 {%0,%1,%2,%3}, [%4];" \
                 : "=r"(r0), "=r"(r1), "=r"(r2), "=r"(r3) : "r"(addr))

#define MMA8(d, a, b0_, b1_)                                                  \
    asm volatile(                                                             \
        "mma.sync.aligned.m16n8k32.row.col.s32.s8.s8.s32 "                   \
        "{%0,%1,%2,%3}, {%4,%5,%6,%7}, {%8,%9}, {%0,%1,%2,%3};\n"            \
        : "+r"(d[0]), "+r"(d[1]), "+r"(d[2]), "+r"(d[3])                     \
        : "r"(a[0]), "r"(a[1]), "r"(a[2]), "r"(a[3]), "r"(b0_), "r"(b1_))

__global__ void __launch_bounds__(256, 2) conv_mma_kernel(float* __restrict__ out) {
    __shared__ signed char As[2][STG_BYTES];
    __shared__ signed char Bs[2][STG_BYTES];

    const int t      = threadIdx.x;
    const int lane   = t & 31;
    const int warp_m = (t >> 5) & 3;   // 0..3
    const int warp_n = t >> 7;         // 0..1
    const int m0     = blockIdx.x * 128;
    const int co0    = blockIdx.y * 128;

    // Loader mapping: thread t -> rows (t/4) and (t/4 + 64), 16B segment t%4
    const int lrow = t >> 2;
    const int lseg = t & 3;

    long abase[2];
    int hi0[2], wi0[2];
    const signed char* bbase[2];
#pragma unroll
    for (int i = 0; i < 2; ++i) {
        int m   = m0 + lrow + i * 64;
        int n   = m / S_OUT;
        int rem = m - n * S_OUT;
        int ho  = rem / WOUT;
        int wo  = rem - ho * WOUT;
        hi0[i] = 2 * ho - 1;
        wi0[i] = 2 * wo - 1;
        abase[i] = ((long)n * S_IN + (long)hi0[i] * WIN + wi0[i]) * CIN + lseg * 16;
        bbase[i] = g_wq + (size_t)(co0 + lrow + i * 64) * 9 * CIN + lseg * 16;
    }

    const uint32_t sA = (uint32_t)__cvta_generic_to_shared(&As[0][0]);
    const uint32_t sB = (uint32_t)__cvta_generic_to_shared(&Bs[0][0]);
    const uint32_t dA0 = sA + lrow * PITCH + lseg * 16;
    const uint32_t dB0 = sB + lrow * PITCH + lseg * 16;

    // ldmatrix lane offsets (verified vs PTX m16n8k32 fragment layout)
    const uint32_t a_lane = (uint32_t)((lane & 15) * PITCH + (lane >> 4) * 16);
    const uint32_t b_lane = (uint32_t)(((lane & 7) + ((lane >> 4) << 3)) * PITCH +
                                       (((lane >> 3) & 1) << 4));
    const uint32_t aBase0 = sA + (warp_m * 32) * PITCH + a_lane;
    const uint32_t bBase0 = sB + (warp_n * 64) * PITCH + b_lane;

    int acc[2][8][4];
#pragma unroll
    for (int mi = 0; mi < 2; ++mi)
#pragma unroll
        for (int ni = 0; ni < 8; ++ni)
#pragma unroll
            for (int k = 0; k < 4; ++k) acc[mi][ni][k] = 0;

    // ---- pipeline ----
    auto issue = [&](int c, int st) {
        int tap = c >> 2;
        int kc  = (c & 3) * 64;
        int kh  = tap / 3;
        int kw  = tap - kh * 3;
        long toff = (long)((kh * WIN + kw) * CIN + kc);
        uint32_t so = (uint32_t)(st * STG_BYTES);
#pragma unroll
        for (int i = 0; i < 2; ++i) {
            bool v = ((unsigned)(hi0[i] + kh) < (unsigned)HIN) &&
                     ((unsigned)(wi0[i] + kw) < (unsigned)WIN);
            const signed char* asrc = v ? (g_xq + abase[i] + toff) : g_xq;
            cp16(dA0 + so + i * (64 * PITCH), asrc, v ? 16 : 0);
            cp16(dB0 + so + i * (64 * PITCH), bbase[i] + tap * CIN + kc, 16);
        }
    };

    issue(0, 0);
    asm volatile("cp.async.commit_group;\n" ::: "memory");

#pragma unroll 1
    for (int c = 0; c < 36; ++c) {
        if (c < 35) {
            issue(c + 1, (c + 1) & 1);
            asm volatile("cp.async.commit_group;\n" ::: "memory");
            asm volatile("cp.async.wait_group 1;\n" ::: "memory");
        } else {
            asm volatile("cp.async.wait_group 0;\n" ::: "memory");
        }
        __syncthreads();

        const uint32_t so = (uint32_t)((c & 1) * STG_BYTES);
        const uint32_t aB = aBase0 + so;
        const uint32_t bB = bBase0 + so;
#pragma unroll
        for (int k2 = 0; k2 < 2; ++k2) {
            const uint32_t kb = k2 * 32;
            uint32_t a[2][4];
            LDSM4(a[0][0], a[0][1], a[0][2], a[0][3], aB + kb);
            LDSM4(a[1][0], a[1][1], a[1][2], a[1][3], aB + 16 * PITCH + kb);
#pragma unroll
            for (int p = 0; p < 4; ++p) {
                uint32_t b0, b1, b2, b3;
                LDSM4(b0, b1, b2, b3, bB + p * (16 * PITCH) + kb);
#pragma unroll
                for (int mi = 0; mi < 2; ++mi) {
                    MMA8(acc[mi][2 * p],     a[mi], b0, b1);
                    MMA8(acc[mi][2 * p + 1], a[mi], b2, b3);
                }
            }
        }
        __syncthreads();
    }

    // Epilogue: dequantize and store NCHW fp32.
    const float sc = (float)(0.05 * 0.01);
#pragma unroll
    for (int mi = 0; mi < 2; ++mi) {
#pragma unroll
        for (int rr = 0; rr < 2; ++rr) {
            int m = m0 + warp_m * 32 + mi * 16 + (lane >> 2) + rr * 8;
            int n = m / S_OUT;
            int s = m - n * S_OUT;
            float* op = out + (size_t)n * COUT * S_OUT + s;
#pragma unroll
            for (int ni = 0; ni < 8; ++ni) {
                int co = co0 + warp_n * 64 + ni * 8 + (lane & 3) * 2;
                op[(size_t)co * S_OUT]       = (float)acc[mi][ni][rr * 2 + 0] * sc;
                op[(size_t)(co + 1) * S_OUT] = (float)acc[mi][ni][rr * 2 + 1] * sc;
            }
        }
    }
}

// ---------------------------------------------------------------------------
extern "C" void kernel_launch(void* const* d_in, const int* in_sizes, int n_in,
                              void* d_out, int out_size) {
    const float* x = (const float*)d_in[0];
    const float* w = (const float*)d_in[1];
    if (n_in >= 2 && in_sizes[0] != X_ELEMS) {
        const float* tmp = x; x = w; w = tmp;
    }
    float* out = (float*)d_out;

    dim3 g1(S_IN / 32, CIN / 128, XN);  // (98, 2, 32)
    quant_x_kernel<<<g1, 256>>>(x);

    quant_w_kernel<<<(COUT * 9 * CIN + 255) / 256, 256>>>(w);

    dim3 g3(M_TOTAL / 128, COUT / 128);  // (196, 2)
    conv_mma_kernel<<<g3, 256>>>(out);
}

// round 7
// speedup vs baseline: 1.8330x; 1.5701x over previous
#include <cuda_runtime.h>
#include <cuda_bf16.h>
#include <cstdint>

#define XN 32
#define CIN 256
#define HIN 56
#define WIN 56
#define S_IN 3136
#define COUT 256
#define HOUT 28
#define WOUT 28
#define S_OUT 784
#define M_TOTAL 25088
#define X_ELEMS (XN * CIN * S_IN)

// Device scratch (no cudaMalloc allowed)
__device__ __align__(16) __nv_bfloat16 g_xq[(size_t)XN * S_IN * CIN];   // 51.4 MB NHWC bf16
__device__ __align__(16) __nv_bfloat16 g_wq[(size_t)COUT * 9 * CIN];    // 1.18 MB [co][tap][ci]

// ---------------------------------------------------------------------------
// Kernel 1: quantize x (round-half-even, clamp [-128,127]) as bf16 +
// NCHW -> N(S)C transpose via smem tile (128 ch x 32 spatial).
// ---------------------------------------------------------------------------
__global__ void quant_x_kernel(const float* __restrict__ x) {
    __shared__ __align__(16) __nv_bfloat16 tile[32 * 130];  // pitch 130 -> conflict-free
    const int n  = blockIdx.z;
    const int c0 = blockIdx.y * 128;
    const int s0 = blockIdx.x * 32;
    const int t  = threadIdx.x;

    const float* xb = x + (size_t)n * CIN * S_IN;
#pragma unroll
    for (int it = 0; it < 16; ++it) {
        int i  = it * 256 + t;
        int cl = i >> 5;   // 0..127
        int sl = i & 31;   // 0..31
        float v = xb[(size_t)(c0 + cl) * S_IN + (s0 + sl)];
        int q = __float2int_rn(v * 20.0f);   // round-half-even == jnp.round
        q = max(-128, min(127, q));
        tile[sl * 130 + cl] = __float2bfloat16((float)q);  // exact (|q|<=128)
    }
    __syncthreads();

    __nv_bfloat16* ob = g_xq + ((size_t)n * S_IN + s0) * CIN + c0;
#pragma unroll
    for (int it = 0; it < 8; ++it) {
        int u  = it * 256 + t;
        int sl = u >> 6;   // 0..31
        int cu = u & 63;   // 0..63 (pairs of channels)
        uint32_t val = *(const uint32_t*)&tile[sl * 130 + cu * 2];
        *(uint32_t*)&ob[(size_t)sl * CIN + cu * 2] = val;
    }
}

// ---------------------------------------------------------------------------
// Kernel 2: weights OIHW fp32 (int-valued) -> [co][tap][ci] bf16 (exact)
// ---------------------------------------------------------------------------
__global__ void quant_w_kernel(const float* __restrict__ w) {
    int idx = blockIdx.x * blockDim.x + threadIdx.x;
    if (idx >= COUT * 9 * CIN) return;
    int co  = idx / (9 * CIN);
    int r   = idx - co * 9 * CIN;
    int tap = r >> 8;
    int ci  = r & 255;
    float v = w[(size_t)co * CIN * 9 + (size_t)ci * 9 + tap];
    g_wq[idx] = __float2bfloat16((float)__float2int_rn(v));
}

// ---------------------------------------------------------------------------
// Kernel 3: implicit GEMM conv, bf16 mma.sync m16n8k16 (real HMMA tensor path;
// the s8 mma.sync path is ALU-emulated on sm_103 at ~68cyc/op).
// CTA tile 128(M) x 128(N). 8 warps: 4(M) x 2(N), warp tile 32x64.
// K: 36 chunks = 9 taps x 4 sub-chunks of 64 channels (4 x k16 per chunk).
// Smem PITCH 144B: rows start at bank 4r mod 32 -> ldmatrix conflict-free.
// 2-stage cp.async pipeline (proven R4 skeleton), dynamic smem 72KB.
// ---------------------------------------------------------------------------
#define PITCH 144
#define TILEB (128 * PITCH)          // 18432 per A or B tile
#define STGB  (2 * TILEB)            // 36864 per stage
#define SMEMT (2 * STGB)             // 73728 (2 stages)

__device__ __forceinline__ void cp16(uint32_t dst, const void* src, int sz) {
    asm volatile("cp.async.ca.shared.global [%0], [%1], 16, %2;\n"
                 :: "r"(dst), "l"(src), "r"(sz));
}

#define LDSM4(r0, r1, r2, r3, addr)                                          \
    asm volatile("ldmatrix.sync.aligned.m8n8.x4.shared.b16 {%0,%1,%2,%3}, [%4];" \
                 : "=r"(r0), "=r"(r1), "=r"(r2), "=r"(r3) : "r"(addr))

#define MMABF16(d, a, b0_, b1_)                                               \
    asm volatile(                                                             \
        "mma.sync.aligned.m16n8k16.row.col.f32.bf16.bf16.f32 "               \
        "{%0,%1,%2,%3}, {%4,%5,%6,%7}, {%8,%9}, {%0,%1,%2,%3};\n"            \
        : "+f"(d[0]), "+f"(d[1]), "+f"(d[2]), "+f"(d[3])                     \
        : "r"(a[0]), "r"(a[1]), "r"(a[2]), "r"(a[3]), "r"(b0_), "r"(b1_))

__global__ void __launch_bounds__(256, 2) conv_mma_kernel(float* __restrict__ out) {
    extern __shared__ char dsm[];
    const uint32_t sbase = (uint32_t)__cvta_generic_to_shared(dsm);

    const int t      = threadIdx.x;
    const int lane   = t & 31;
    const int warp_m = (t >> 5) & 3;   // 0..3
    const int warp_n = t >> 7;         // 0..1
    const int m0     = blockIdx.x * 128;
    const int co0    = blockIdx.y * 128;

    // Loader: thread t -> row t/2 (0..127), 64B half t%2 (4 x 16B segments)
    const int lrow  = t >> 1;
    const int lhalf = t & 1;

    int m   = m0 + lrow;
    int n   = m / S_OUT;
    int rem = m - n * S_OUT;
    int ho  = rem / WOUT;
    int wo  = rem - ho * WOUT;
    const int hb = 2 * ho - 1;
    const int wb = 2 * wo - 1;
    const __nv_bfloat16* an = g_xq + (size_t)n * S_IN * CIN + lhalf * 32;
    const __nv_bfloat16* bw = g_wq + (size_t)(co0 + lrow) * 9 * CIN + lhalf * 32;

    const uint32_t dstA = sbase + (uint32_t)(lrow * PITCH + lhalf * 64);
    const uint32_t dstB = dstA + TILEB;

    // ldmatrix lane offsets (same conventions as verified R4 fragment order)
    const uint32_t a_lane = (uint32_t)((lane & 15) * PITCH + (lane >> 4) * 16);
    const uint32_t b_lane = (uint32_t)(((lane & 7) + ((lane >> 4) << 3)) * PITCH +
                                       (((lane >> 3) & 1) << 4));
    const uint32_t aBase0 = sbase + (warp_m * 32) * PITCH + a_lane;
    const uint32_t bBase0 = sbase + TILEB + (warp_n * 64) * PITCH + b_lane;

    float acc[2][8][4];
#pragma unroll
    for (int mi = 0; mi < 2; ++mi)
#pragma unroll
        for (int ni = 0; ni < 8; ++ni)
#pragma unroll
            for (int k = 0; k < 4; ++k) acc[mi][ni][k] = 0.0f;

    auto issue = [&](int c, int st) {
        int tap = c >> 2;
        int kc  = (c & 3) * 64;
        int kh  = tap / 3;
        int kw  = tap - kh * 3;
        int hi  = hb + kh, wi = wb + kw;
        bool v  = ((unsigned)hi < (unsigned)HIN) && ((unsigned)wi < (unsigned)WIN);
        const __nv_bfloat16* asrc = an + ((size_t)(hi * WIN + wi) * CIN + kc);
        const __nv_bfloat16* bsrc = bw + (tap * CIN + kc);
        uint32_t so = (uint32_t)(st * STGB);
#pragma unroll
        for (int i = 0; i < 4; ++i) {
            cp16(dstA + so + i * 16, v ? (const void*)(asrc + i * 8) : (const void*)g_xq,
                 v ? 16 : 0);
            cp16(dstB + so + i * 16, bsrc + i * 8, 16);
        }
    };

    issue(0, 0);
    asm volatile("cp.async.commit_group;\n" ::: "memory");

#pragma unroll 1
    for (int c = 0; c < 36; ++c) {
        if (c < 35) {
            issue(c + 1, (c + 1) & 1);
            asm volatile("cp.async.commit_group;\n" ::: "memory");
            asm volatile("cp.async.wait_group 1;\n" ::: "memory");
        } else {
            asm volatile("cp.async.wait_group 0;\n" ::: "memory");
        }
        __syncthreads();

        const uint32_t so = (uint32_t)((c & 1) * STGB);
        const uint32_t aB = aBase0 + so;
        const uint32_t bB = bBase0 + so;
#pragma unroll
        for (int ks = 0; ks < 4; ++ks) {
            const uint32_t kb = ks * 32;   // 16 bf16 per k-step
            uint32_t a[2][4];
            LDSM4(a[0][0], a[0][1], a[0][2], a[0][3], aB + kb);
            LDSM4(a[1][0], a[1][1], a[1][2], a[1][3], aB + 16 * PITCH + kb);
#pragma unroll
            for (int p = 0; p < 4; ++p) {
                uint32_t b0, b1, b2, b3;
                LDSM4(b0, b1, b2, b3, bB + p * (16 * PITCH) + kb);
#pragma unroll
                for (int mi = 0; mi < 2; ++mi) {
                    MMABF16(acc[mi][2 * p],     a[mi], b0, b1);
                    MMABF16(acc[mi][2 * p + 1], a[mi], b2, b3);
                }
            }
        }
        __syncthreads();
    }

    // Epilogue: dequantize and store NCHW fp32 (acc already exact integers).
    const float sc = (float)(0.05 * 0.01);
#pragma unroll
    for (int mi = 0; mi < 2; ++mi) {
#pragma unroll
        for (int rr = 0; rr < 2; ++rr) {
            int mm = m0 + warp_m * 32 + mi * 16 + (lane >> 2) + rr * 8;
            int nn = mm / S_OUT;
            int ss = mm - nn * S_OUT;
            float* op = out + (size_t)nn * COUT * S_OUT + ss;
#pragma unroll
            for (int ni = 0; ni < 8; ++ni) {
                int co = co0 + warp_n * 64 + ni * 8 + (lane & 3) * 2;
                op[(size_t)co * S_OUT]       = acc[mi][ni][rr * 2 + 0] * sc;
                op[(size_t)(co + 1) * S_OUT] = acc[mi][ni][rr * 2 + 1] * sc;
            }
        }
    }
}

// ---------------------------------------------------------------------------
extern "C" void kernel_launch(void* const* d_in, const int* in_sizes, int n_in,
                              void* d_out, int out_size) {
    const float* x = (const float*)d_in[0];
    const float* w = (const float*)d_in[1];
    if (n_in >= 2 && in_sizes[0] != X_ELEMS) {
        const float* tmp = x; x = w; w = tmp;
    }
    float* out = (float*)d_out;

    dim3 g1(S_IN / 32, CIN / 128, XN);  // (98, 2, 32)
    quant_x_kernel<<<g1, 256>>>(x);

    quant_w_kernel<<<(COUT * 9 * CIN + 255) / 256, 256>>>(w);

    cudaFuncSetAttribute(conv_mma_kernel,
                         cudaFuncAttributeMaxDynamicSharedMemorySize, SMEMT);
    dim3 g3(M_TOTAL / 128, COUT / 128);  // (196, 2)
    conv_mma_kernel<<<g3, 256, SMEMT>>>(out);
}